// round 1
// baseline (speedup 1.0000x reference)
#include <cuda_runtime.h>
#include <cuda_bf16.h>

// ---------------------------------------------------------------------------
// RecurrentRetention: B=16, T=2048, D=256, gamma=0.9
//
// Algebraic collapse:
//   vsum[b,t]   = x[b,t,:] . rowsum(Wv)                 (matvec)
//   y[t,e]      = sum_b vsum[b,t] * x[b,t,e]            (fused with vsum)
//   c           = y @ Wk                                ([2048,256]x[256,256])
//   r[t,d]      = 0.9 r[t-1,d] + c[t,d],  t = 1..T-1    (scan, windowed)
//   S[0]=r[1], S[t]=r[t]
//   out[b,q,p]  = S[8p + (q>>8), q&255] * (x @ Wq)[b,q,p]
// ---------------------------------------------------------------------------

#define Bsz 16
#define T   2048
#define D   256

__device__ float g_wvsum[D];
__device__ float g_y[T * D];
__device__ float g_c[T * D];
__device__ float g_S[T * D];

// --- K1: rowsum of Wv -------------------------------------------------------
__global__ void wvsum_kernel(const float* __restrict__ Wv) {
    int row  = blockIdx.x * 8 + (threadIdx.x >> 5);
    int lane = threadIdx.x & 31;
    float p = 0.f;
    #pragma unroll
    for (int j = lane; j < D; j += 32) p += Wv[row * D + j];
    #pragma unroll
    for (int off = 16; off; off >>= 1) p += __shfl_xor_sync(0xffffffffu, p, off);
    if (lane == 0) g_wvsum[row] = p;
}

// --- K2: y[t,e] = sum_b (x[b,t,:].wvsum) * x[b,t,e] ------------------------
__global__ void y_kernel(const float* __restrict__ x) {
    __shared__ float xs[Bsz][D];
    __shared__ float vs[Bsz];
    __shared__ float wv[D];
    int t = blockIdx.x;
    int e = threadIdx.x;

    wv[e] = g_wvsum[e];
    #pragma unroll
    for (int b = 0; b < Bsz; ++b)
        xs[b][e] = x[((size_t)b * T + t) * D + e];
    __syncthreads();

    int warp = e >> 5, lane = e & 31;
    #pragma unroll
    for (int rep = 0; rep < 2; ++rep) {
        int b = warp * 2 + rep;
        float p = 0.f;
        #pragma unroll
        for (int k = lane; k < D; k += 32) p += xs[b][k] * wv[k];
        #pragma unroll
        for (int off = 16; off; off >>= 1) p += __shfl_xor_sync(0xffffffffu, p, off);
        if (lane == 0) vs[b] = p;
    }
    __syncthreads();

    float acc = 0.f;
    #pragma unroll
    for (int b = 0; b < Bsz; ++b) acc += vs[b] * xs[b][e];
    g_y[t * D + e] = acc;
}

// --- K3/K5: 64x64-tile SGEMM, N=K=256 fixed; optional scramble epilogue ----
// C[m,n] = sum_k A[m,k]*Bw[k,n];  if scale: *= g_S[(8n + (t>>8))*256 + (t&255)]
__global__ void __launch_bounds__(256)
sgemm64(const float* __restrict__ A, const float* __restrict__ Bw,
        float* __restrict__ C, int apply_scale) {
    __shared__ float As[64][16];
    __shared__ float Bs[16][68];   // padded to dodge conflicts

    int m0 = blockIdx.x * 64, n0 = blockIdx.y * 64;
    int tid = threadIdx.x;
    int tx = tid & 15, ty = tid >> 4;

    // load maps (float4)
    int ar = tid >> 2,  ac = (tid & 3)  * 4;   // A tile: 64x16
    int br = tid >> 4,  bc = (tid & 15) * 4;   // B tile: 16x64

    float acc[4][4] = {};

    for (int k0 = 0; k0 < 256; k0 += 16) {
        float4 av = *(const float4*)&A[(size_t)(m0 + ar) * 256 + k0 + ac];
        float4 bv = *(const float4*)&Bw[(size_t)(k0 + br) * 256 + n0 + bc];
        __syncthreads();                 // prior tile fully consumed
        As[ar][ac+0] = av.x; As[ar][ac+1] = av.y;
        As[ar][ac+2] = av.z; As[ar][ac+3] = av.w;
        Bs[br][bc+0] = bv.x; Bs[br][bc+1] = bv.y;
        Bs[br][bc+2] = bv.z; Bs[br][bc+3] = bv.w;
        __syncthreads();

        #pragma unroll
        for (int kk = 0; kk < 16; ++kk) {
            float a[4], b[4];
            #pragma unroll
            for (int i = 0; i < 4; ++i) a[i] = As[ty*4 + i][kk];
            #pragma unroll
            for (int j = 0; j < 4; ++j) b[j] = Bs[kk][tx*4 + j];
            #pragma unroll
            for (int i = 0; i < 4; ++i)
                #pragma unroll
                for (int j = 0; j < 4; ++j)
                    acc[i][j] = fmaf(a[i], b[j], acc[i][j]);
        }
    }

    #pragma unroll
    for (int i = 0; i < 4; ++i) {
        int m = m0 + ty*4 + i;
        int t = m & (T - 1);
        #pragma unroll
        for (int j = 0; j < 4; ++j) {
            int n = n0 + tx*4 + j;
            float v = acc[i][j];
            if (apply_scale)
                v *= g_S[((n << 3) + (t >> 8)) * D + (t & 255)];
            C[(size_t)m * 256 + n] = v;
        }
    }
}

// --- K4: windowed scan over t ----------------------------------------------
__global__ void scan_kernel() {
    int d = threadIdx.x;
    int g = blockIdx.x;
    int tile_start = g * 256;
    int t0 = (g == 0) ? 1 : tile_start - 256;   // 256-step warmup; gamma^256 ~ 2e-12
    float s = 0.f;
    for (int t = t0; t < tile_start + 256; ++t) {
        s = 0.9f * s + g_c[t * D + d];
        if (t >= tile_start) g_S[t * D + d] = s;
        if (g == 0 && t == 1) g_S[d] = s;       // S[0] = r[1]
    }
}

extern "C" void kernel_launch(void* const* d_in, const int* in_sizes, int n_in,
                              void* d_out, int out_size) {
    const float* x  = (const float*)d_in[0];
    const float* Wq = (const float*)d_in[1];
    const float* Wk = (const float*)d_in[2];
    const float* Wv = (const float*)d_in[3];
    float* out = (float*)d_out;

    float* y_p; cudaGetSymbolAddress((void**)&y_p, g_y);
    float* c_p; cudaGetSymbolAddress((void**)&c_p, g_c);

    // 1. rowsum(Wv)
    wvsum_kernel<<<32, 256>>>(Wv);
    // 2. y[t,:]
    y_kernel<<<T, 256>>>(x);
    // 3. c = y @ Wk
    {
        dim3 grid(T / 64, D / 64);
        sgemm64<<<grid, 256>>>(y_p, Wk, c_p, 0);
    }
    // 4. scan -> S
    scan_kernel<<<T / 256, 256>>>();
    // 5. out = (x @ Wq) * scramble(S)
    {
        dim3 grid((Bsz * T) / 64, D / 64);
        sgemm64<<<grid, 256>>>(x, Wq, out, 1);
    }
}

// round 3
// speedup vs baseline: 1.5909x; 1.5909x over previous
#include <cuda_runtime.h>
#include <cuda_bf16.h>

// ---------------------------------------------------------------------------
// RecurrentRetention: B=16, T=2048, D=256, gamma=0.9
//
//   vsum[b,t]   = x[b,t,:] . rowsum(Wv)
//   y[t,e]      = sum_b vsum[b,t] * x[b,t,e]
//   c           = y @ Wk
//   r[t,d]      = 0.9 r[t-1,d] + c[t,d]   (r[0]=0, c[0] dropped) — exact 3-phase scan
//   S[0]=r[1], S[t]=r[t]
//   out[b,q,p]  = S[8p + (q>>8), q&255] * (x @ Wq)[b,q,p]
// ---------------------------------------------------------------------------

#define Bsz 16
#define T   2048
#define D   256
#define LTILE 32                      // scan tile length
#define NTILE (T / LTILE)             // 64

__device__ float g_wvsum[D];
__device__ float g_y[T * D];
__device__ float g_c[T * D];
__device__ float g_S[T * D];
__device__ float g_carry[NTILE * D];  // carry out of each tile
__device__ float g_pref[NTILE * D];   // carry entering each tile

// --- K1: rowsum of Wv -------------------------------------------------------
__global__ void wvsum_kernel(const float* __restrict__ Wv) {
    int row  = blockIdx.x * 8 + (threadIdx.x >> 5);
    int lane = threadIdx.x & 31;
    float p = 0.f;
    #pragma unroll
    for (int j = lane; j < D; j += 32) p += Wv[row * D + j];
    #pragma unroll
    for (int off = 16; off; off >>= 1) p += __shfl_xor_sync(0xffffffffu, p, off);
    if (lane == 0) g_wvsum[row] = p;
}

// --- K2: y[t,e] = sum_b (x[b,t,:].wvsum) * x[b,t,e] ------------------------
__global__ void y_kernel(const float* __restrict__ x) {
    __shared__ float xs[Bsz][D];
    __shared__ float vs[Bsz];
    __shared__ float wv[D];
    int t = blockIdx.x;
    int e = threadIdx.x;

    wv[e] = g_wvsum[e];
    #pragma unroll
    for (int b = 0; b < Bsz; ++b)
        xs[b][e] = x[((size_t)b * T + t) * D + e];
    __syncthreads();

    int warp = e >> 5, lane = e & 31;
    #pragma unroll
    for (int rep = 0; rep < 2; ++rep) {
        int b = warp * 2 + rep;
        float p = 0.f;
        #pragma unroll
        for (int k = lane; k < D; k += 32) p += xs[b][k] * wv[k];
        #pragma unroll
        for (int off = 16; off; off >>= 1) p += __shfl_xor_sync(0xffffffffu, p, off);
        if (lane == 0) vs[b] = p;
    }
    __syncthreads();

    float acc = 0.f;
    #pragma unroll
    for (int b = 0; b < Bsz; ++b) acc += vs[b] * xs[b][e];
    g_y[t * D + e] = acc;
}

// --- K3/K6: 64x64-tile SGEMM, N=K=256 fixed; optional scramble epilogue ----
__global__ void __launch_bounds__(256)
sgemm64(const float* __restrict__ A, const float* __restrict__ Bw,
        float* __restrict__ C, int apply_scale) {
    __shared__ float As[64][16];
    __shared__ float Bs[16][68];

    int m0 = blockIdx.x * 64, n0 = blockIdx.y * 64;
    int tid = threadIdx.x;
    int tx = tid & 15, ty = tid >> 4;

    int ar = tid >> 2,  ac = (tid & 3)  * 4;   // A tile: 64x16
    int br = tid >> 4,  bc = (tid & 15) * 4;   // B tile: 16x64

    float acc[4][4] = {};

    for (int k0 = 0; k0 < 256; k0 += 16) {
        float4 av = *(const float4*)&A[(size_t)(m0 + ar) * 256 + k0 + ac];
        float4 bv = *(const float4*)&Bw[(size_t)(k0 + br) * 256 + n0 + bc];
        __syncthreads();
        As[ar][ac+0] = av.x; As[ar][ac+1] = av.y;
        As[ar][ac+2] = av.z; As[ar][ac+3] = av.w;
        Bs[br][bc+0] = bv.x; Bs[br][bc+1] = bv.y;
        Bs[br][bc+2] = bv.z; Bs[br][bc+3] = bv.w;
        __syncthreads();

        #pragma unroll
        for (int kk = 0; kk < 16; ++kk) {
            float a[4], b[4];
            #pragma unroll
            for (int i = 0; i < 4; ++i) a[i] = As[ty*4 + i][kk];
            #pragma unroll
            for (int j = 0; j < 4; ++j) b[j] = Bs[kk][tx*4 + j];
            #pragma unroll
            for (int i = 0; i < 4; ++i)
                #pragma unroll
                for (int j = 0; j < 4; ++j)
                    acc[i][j] = fmaf(a[i], b[j], acc[i][j]);
        }
    }

    #pragma unroll
    for (int i = 0; i < 4; ++i) {
        int m = m0 + ty*4 + i;
        int t = m & (T - 1);
        #pragma unroll
        for (int j = 0; j < 4; ++j) {
            int n = n0 + tx*4 + j;
            float v = acc[i][j];
            if (apply_scale)
                v *= g_S[((n << 3) + (t >> 8)) * D + (t & 255)];
            C[(size_t)m * 256 + n] = v;
        }
    }
}

// --- K4a: per-tile local scan + carry (exact) ------------------------------
__global__ void scanA_kernel() {
    int d = threadIdx.x;
    int g = blockIdx.x;
    int t0 = g * LTILE;
    float s = 0.f;
    #pragma unroll
    for (int i = 0; i < LTILE; ++i) {
        int t = t0 + i;
        float cv = (t == 0) ? 0.f : g_c[t * D + d];  // c[0] never contributes
        s = 0.9f * s + cv;
        g_S[t * D + d] = s;
    }
    g_carry[g * D + d] = s;
}

// --- K4b: serial combine across 64 tiles (tiny) ----------------------------
__global__ void scanB_kernel() {
    int d = threadIdx.x;
    const float g32 = 0.03433683820f;   // 0.9^32
    float carry = 0.f;
    #pragma unroll
    for (int g = 0; g < NTILE; ++g) {
        float tmp = g_carry[g * D + d];
        g_pref[g * D + d] = carry;
        carry = g32 * carry + tmp;
    }
}

// --- K4c: fix-up with incoming carry; set S[0]=r[1] ------------------------
__global__ void scanC_kernel() {
    int d = threadIdx.x;
    int g = blockIdx.x;
    int t0 = g * LTILE;
    float pref = g_pref[g * D + d];
    if (g > 0) {
        float p = 0.9f;
        #pragma unroll
        for (int i = 0; i < LTILE; ++i) {
            g_S[(t0 + i) * D + d] += p * pref;
            p *= 0.9f;
        }
    } else {
        // this thread owns column d for all t in tile 0; no cross-thread dep
        g_S[d] = g_S[D + d];            // S[0] = r[1]
    }
}

extern "C" void kernel_launch(void* const* d_in, const int* in_sizes, int n_in,
                              void* d_out, int out_size) {
    const float* x  = (const float*)d_in[0];
    const float* Wq = (const float*)d_in[1];
    const float* Wk = (const float*)d_in[2];
    const float* Wv = (const float*)d_in[3];
    float* out = (float*)d_out;

    float* y_p; cudaGetSymbolAddress((void**)&y_p, g_y);
    float* c_p; cudaGetSymbolAddress((void**)&c_p, g_c);

    wvsum_kernel<<<32, 256>>>(Wv);
    y_kernel<<<T, 256>>>(x);
    {
        dim3 grid(T / 64, D / 64);
        sgemm64<<<grid, 256>>>(y_p, Wk, c_p, 0);
    }
    scanA_kernel<<<NTILE, 256>>>();
    scanB_kernel<<<1, 256>>>();
    scanC_kernel<<<NTILE, 256>>>();
    {
        dim3 grid((Bsz * T) / 64, D / 64);
        sgemm64<<<grid, 256>>>(x, Wq, out, 1);
    }
}

// round 5
// speedup vs baseline: 2.3166x; 1.4561x over previous
#include <cuda_runtime.h>
#include <cuda_bf16.h>
#include <cstdint>

// ---------------------------------------------------------------------------
// RecurrentRetention: B=16, T=2048, D=256, gamma=0.9
//   vsum[b,t] = x[b,t,:].rowsum(Wv);  y[t,e] = sum_b vsum[b,t]*x[b,t,e]
//   c = y @ Wk;  r[t] = 0.9 r[t-1] + c[t] (exact 3-phase scan) -> S
//   out[b,q,p] = S[8p+(q>>8), q&255] * (x @ Wq)[b,q,p]
// Final GEMM via warp-level mma.sync bf16 (split: Ah*Bh + Ah*Bl + Al*Bh).
// NOTE: harness PTX pass targets plain sm_103 -> tcgen05 unavailable; mma.sync
// is standard PTX and compiles everywhere.
// ---------------------------------------------------------------------------

#define Bsz 16
#define T   2048
#define D   256
#define LTILE 16
#define NTILE (T / LTILE)             // 128
#define G16 0.1853020188851841f       // 0.9^16

__device__ float g_wvsum[D];
__device__ float g_y[T * D];
__device__ float g_c[T * D];
__device__ float g_S[T * D];
__device__ float g_carry[NTILE * D];
__device__ float g_pref[NTILE * D];
__device__ __nv_bfloat16 g_xh[Bsz * T * D];
__device__ __nv_bfloat16 g_xl[Bsz * T * D];
__device__ __nv_bfloat16 g_bh[D * D];   // Wq^T hi, [n][k]
__device__ __nv_bfloat16 g_bl[D * D];   // Wq^T lo

__device__ __forceinline__ uint32_t smem_u32(const void* p) {
    uint32_t a;
    asm("{ .reg .u64 t; cvta.to.shared.u64 t, %1; cvt.u32.u64 %0, t; }" : "=r"(a) : "l"(p));
    return a;
}
__device__ __forceinline__ void ldm_x4(uint32_t* r, uint32_t addr) {
    asm volatile("ldmatrix.sync.aligned.m8n8.x4.shared.b16 {%0,%1,%2,%3}, [%4];"
        : "=r"(r[0]), "=r"(r[1]), "=r"(r[2]), "=r"(r[3]) : "r"(addr));
}
__device__ __forceinline__ void ldm_x2(uint32_t* r, uint32_t addr) {
    asm volatile("ldmatrix.sync.aligned.m8n8.x2.shared.b16 {%0,%1}, [%2];"
        : "=r"(r[0]), "=r"(r[1]) : "r"(addr));
}
__device__ __forceinline__ void mma_bf16(float* c, const uint32_t* a, const uint32_t* b) {
    asm volatile(
        "mma.sync.aligned.m16n8k16.row.col.f32.bf16.bf16.f32 "
        "{%0,%1,%2,%3}, {%4,%5,%6,%7}, {%8,%9}, {%0,%1,%2,%3};"
        : "+f"(c[0]), "+f"(c[1]), "+f"(c[2]), "+f"(c[3])
        : "r"(a[0]), "r"(a[1]), "r"(a[2]), "r"(a[3]), "r"(b[0]), "r"(b[1]));
}

// ======================= small kernels =====================================
__global__ void wvsum_kernel(const float* __restrict__ Wv) {
    int row  = blockIdx.x * 8 + (threadIdx.x >> 5);
    int lane = threadIdx.x & 31;
    float p = 0.f;
    #pragma unroll
    for (int j = lane; j < D; j += 32) p += Wv[row * D + j];
    #pragma unroll
    for (int off = 16; off; off >>= 1) p += __shfl_xor_sync(0xffffffffu, p, off);
    if (lane == 0) g_wvsum[row] = p;
}

// Wq^T split to bf16 hi/lo.  grid=(256): block k, thread n
__global__ void wqconv_kernel(const float* __restrict__ Wq) {
    int k = blockIdx.x, n = threadIdx.x;
    float w = Wq[k * D + n];
    __nv_bfloat16 h = __float2bfloat16(w);
    g_bh[n * D + k] = h;
    g_bl[n * D + k] = __float2bfloat16(w - __bfloat162float(h));
}

// y + x split conversion
__global__ void y_kernel(const float* __restrict__ x) {
    __shared__ float xs[Bsz][D];
    __shared__ float vs[Bsz];
    __shared__ float wv[D];
    int t = blockIdx.x;
    int e = threadIdx.x;

    wv[e] = g_wvsum[e];
    #pragma unroll
    for (int b = 0; b < Bsz; ++b) {
        size_t idx = ((size_t)b * T + t) * D + e;
        float v = x[idx];
        xs[b][e] = v;
        __nv_bfloat16 h = __float2bfloat16(v);
        g_xh[idx] = h;
        g_xl[idx] = __float2bfloat16(v - __bfloat162float(h));
    }
    __syncthreads();

    int warp = e >> 5, lane = e & 31;
    #pragma unroll
    for (int rep = 0; rep < 2; ++rep) {
        int b = warp * 2 + rep;
        float p = 0.f;
        #pragma unroll
        for (int k = lane; k < D; k += 32) p += xs[b][k] * wv[k];
        #pragma unroll
        for (int off = 16; off; off >>= 1) p += __shfl_xor_sync(0xffffffffu, p, off);
        if (lane == 0) vs[b] = p;
    }
    __syncthreads();

    float acc = 0.f;
    #pragma unroll
    for (int b = 0; b < Bsz; ++b) acc += vs[b] * xs[b][e];
    g_y[t * D + e] = acc;
}

// FFMA SGEMM for c = y @ Wk  (small: 0.27 GFLOP)
__global__ void __launch_bounds__(256)
sgemm64(const float* __restrict__ A, const float* __restrict__ Bw, float* __restrict__ C) {
    __shared__ float As[64][16];
    __shared__ float Bs[16][68];
    int m0 = blockIdx.x * 64, n0 = blockIdx.y * 64;
    int tid = threadIdx.x;
    int tx = tid & 15, ty = tid >> 4;
    int ar = tid >> 2,  ac = (tid & 3)  * 4;
    int br = tid >> 4,  bc = (tid & 15) * 4;
    float acc[4][4] = {};
    for (int k0 = 0; k0 < 256; k0 += 16) {
        float4 av = *(const float4*)&A[(size_t)(m0 + ar) * 256 + k0 + ac];
        float4 bv = *(const float4*)&Bw[(size_t)(k0 + br) * 256 + n0 + bc];
        __syncthreads();
        As[ar][ac+0] = av.x; As[ar][ac+1] = av.y; As[ar][ac+2] = av.z; As[ar][ac+3] = av.w;
        Bs[br][bc+0] = bv.x; Bs[br][bc+1] = bv.y; Bs[br][bc+2] = bv.z; Bs[br][bc+3] = bv.w;
        __syncthreads();
        #pragma unroll
        for (int kk = 0; kk < 16; ++kk) {
            float a[4], b[4];
            #pragma unroll
            for (int i = 0; i < 4; ++i) a[i] = As[ty*4 + i][kk];
            #pragma unroll
            for (int j = 0; j < 4; ++j) b[j] = Bs[kk][tx*4 + j];
            #pragma unroll
            for (int i = 0; i < 4; ++i)
                #pragma unroll
                for (int j = 0; j < 4; ++j)
                    acc[i][j] = fmaf(a[i], b[j], acc[i][j]);
        }
    }
    #pragma unroll
    for (int i = 0; i < 4; ++i)
        #pragma unroll
        for (int j = 0; j < 4; ++j)
            C[(size_t)(m0 + ty*4 + i) * 256 + n0 + tx*4 + j] = acc[i][j];
}

// ---- exact 3-phase scan ----
__global__ void scanA_kernel() {
    int d = threadIdx.x, g = blockIdx.x;
    int t0 = g * LTILE;
    float s = 0.f;
    #pragma unroll
    for (int i = 0; i < LTILE; ++i) {
        int t = t0 + i;
        float cv = (t == 0) ? 0.f : g_c[t * D + d];
        s = 0.9f * s + cv;
        g_S[t * D + d] = s;
    }
    g_carry[g * D + d] = s;
}
__global__ void scanB_kernel() {
    int d = threadIdx.x;
    float carry = 0.f;
    #pragma unroll
    for (int g = 0; g < NTILE; ++g) {
        float tmp = g_carry[g * D + d];
        g_pref[g * D + d] = carry;
        carry = G16 * carry + tmp;
    }
}
__global__ void scanC_kernel() {
    int d = threadIdx.x, g = blockIdx.x;
    int t0 = g * LTILE;
    if (g > 0) {
        float pref = g_pref[g * D + d];
        float p = 0.9f;
        #pragma unroll
        for (int i = 0; i < LTILE; ++i) {
            g_S[(t0 + i) * D + d] += p * pref;
            p *= 0.9f;
        }
    } else {
        g_S[d] = g_S[D + d];    // S[0] = r[1]
    }
}

// ======================= mma.sync final GEMM ================================
// out[m,n] = (x@Wq)[m,n] * S[8n + (q>>8), q&255],  q = m & 2047
// grid (256, 2): CTA tile 128x128. 8 warps = 2(m) x 4(n), warp tile 64x32.
// K loop: 8 chunks of 32; per chunk 3 passes (AhBh, AhBl, AlBh).
#define ROWB 80                       // 64B data + 16B pad: conflict-free ldmatrix
__global__ void __launch_bounds__(256, 2)
qgemm_mma(const __nv_bfloat16* __restrict__ xh, const __nv_bfloat16* __restrict__ xl,
          const __nv_bfloat16* __restrict__ bh, const __nv_bfloat16* __restrict__ bl,
          float* __restrict__ out) {
    __shared__ char sAh[128 * ROWB], sAl[128 * ROWB];
    __shared__ char sBh[128 * ROWB], sBl[128 * ROWB];

    int tid = threadIdx.x, wid = tid >> 5, lane = tid & 31;
    int m0 = blockIdx.x * 128, n0 = blockIdx.y * 128;
    int mwarp = (wid & 1) * 64, nwarp = (wid >> 1) * 32;

    uint32_t uAh = smem_u32(sAh), uAl = smem_u32(sAl);
    uint32_t uBh = smem_u32(sBh), uBl = smem_u32(sBl);

    float acc[4][4][4] = {};

    int arow = lane & 15, ao16 = (lane >> 4) * 16;
    int brow = lane & 7,  bo16 = ((lane >> 3) & 1) * 16;

    for (int kc = 0; kc < 8; ++kc) {
        __syncthreads();
        // load Ah/Al/Bh/Bl chunks [128 x 32] bf16, 16B per store, padded rows
        #pragma unroll
        for (int j = 0; j < 2; ++j) {
            int i = tid + j * 256;          // 0..511
            int r = i >> 2, c16 = (i & 3);
            size_t goff = (size_t)r * 256 + kc * 32 + c16 * 8;
            uint32_t soff = r * ROWB + c16 * 16;
            *(uint4*)(sAh + soff) = *(const uint4*)(xh + (size_t)m0 * 256 + goff);
            *(uint4*)(sAl + soff) = *(const uint4*)(xl + (size_t)m0 * 256 + goff);
            *(uint4*)(sBh + soff) = *(const uint4*)(bh + (size_t)n0 * 256 + goff);
            *(uint4*)(sBl + soff) = *(const uint4*)(bl + (size_t)n0 * 256 + goff);
        }
        __syncthreads();

        #pragma unroll
        for (int pass = 0; pass < 3; ++pass) {
            uint32_t uA = (pass < 2) ? uAh : uAl;
            uint32_t uB = (pass == 1) ? uBl : uBh;
            #pragma unroll
            for (int kk = 0; kk < 2; ++kk) {   // two k16 steps per 32-chunk
                uint32_t af[4][4], bf[4][2];
                #pragma unroll
                for (int mf = 0; mf < 4; ++mf)
                    ldm_x4(af[mf], uA + (mwarp + mf * 16 + arow) * ROWB + kk * 32 + ao16);
                #pragma unroll
                for (int nf = 0; nf < 4; ++nf)
                    ldm_x2(bf[nf], uB + (nwarp + nf * 8 + brow) * ROWB + kk * 32 + bo16);
                #pragma unroll
                for (int mf = 0; mf < 4; ++mf)
                    #pragma unroll
                    for (int nf = 0; nf < 4; ++nf)
                        mma_bf16(acc[mf][nf], af[mf], bf[nf]);
            }
        }
    }

    // ---- epilogue: scramble-scale + float2 stores ----
    int tq = lane >> 2, tr = (lane & 3) * 2;
    #pragma unroll
    for (int mf = 0; mf < 4; ++mf) {
        #pragma unroll
        for (int half = 0; half < 2; ++half) {
            int m = m0 + mwarp + mf * 16 + tq + half * 8;
            int q = m & (T - 1);
            int qh = q >> 8, qc = q & 255;
            size_t obase = (size_t)m * 256;
            #pragma unroll
            for (int nf = 0; nf < 4; ++nf) {
                int n = n0 + nwarp + nf * 8 + tr;
                float s0 = g_S[(((n + 0) << 3) + qh) * 256 + qc];
                float s1 = g_S[(((n + 1) << 3) + qh) * 256 + qc];
                float2 v;
                v.x = acc[mf][nf][half * 2 + 0] * s0;
                v.y = acc[mf][nf][half * 2 + 1] * s1;
                *(float2*)(out + obase + n) = v;
            }
        }
    }
}

// ======================= launch ============================================
extern "C" void kernel_launch(void* const* d_in, const int* in_sizes, int n_in,
                              void* d_out, int out_size) {
    const float* x  = (const float*)d_in[0];
    const float* Wq = (const float*)d_in[1];
    const float* Wk = (const float*)d_in[2];
    const float* Wv = (const float*)d_in[3];
    float* out = (float*)d_out;

    float* y_p; cudaGetSymbolAddress((void**)&y_p, g_y);
    float* c_p; cudaGetSymbolAddress((void**)&c_p, g_c);
    __nv_bfloat16* xh_p; cudaGetSymbolAddress((void**)&xh_p, g_xh);
    __nv_bfloat16* xl_p; cudaGetSymbolAddress((void**)&xl_p, g_xl);
    __nv_bfloat16* bh_p; cudaGetSymbolAddress((void**)&bh_p, g_bh);
    __nv_bfloat16* bl_p; cudaGetSymbolAddress((void**)&bl_p, g_bl);

    wvsum_kernel<<<32, 256>>>(Wv);
    wqconv_kernel<<<256, 256>>>(Wq);
    y_kernel<<<T, 256>>>(x);
    {
        dim3 grid(T / 64, D / 64);
        sgemm64<<<grid, 256>>>(y_p, Wk, c_p);
    }
    scanA_kernel<<<NTILE, 256>>>();
    scanB_kernel<<<1, 256>>>();
    scanC_kernel<<<NTILE, 256>>>();
    {
        dim3 grid(Bsz * T / 128, D / 128);
        qgemm_mma<<<grid, 256>>>(xh_p, xl_p, bh_p, bl_p, out);
    }
}